// round 16
// baseline (speedup 1.0000x reference)
#include <cuda_runtime.h>
#include <cuda_bf16.h>
#include <cstdint>

#define NN 50000
#define RR 16
#define DD 200
#define EE 400000
#define KPAD 256

#define NSEG (RR * NN)
#define NBLK ((NSEG + 1023) / 1024)

#define ATILE 8192                      // 64 rows x 128B (one chunk, one half)
#define B_OFF (2 * ATILE)               // Ah @0, Al @ATILE
#define BBYTES 27648                    // 216 rows x 128B (pad for ldsm overreach)
#define SMEM_TOTAL (B_OFF + 2 * BBYTES) // 71680 -> 2 CTAs/SM

// ---------------- scratch (device globals) ----------------------------------
__device__ __align__(128) __nv_bfloat16 g_Bh[17 * DD * KPAD];  // [slot][n][k], slot16=root
__device__ __align__(128) __nv_bfloat16 g_Bl[17 * DD * KPAD];
__device__ int   g_cnt[NSEG];
__device__ int   g_cur[NSEG];
__device__ int   g_off[NSEG];
__device__ int   g_bsum[1024];
__device__ int   g_srcids[EE];
__device__ int   g_list[NSEG];
__device__ int   g_listcnt[RR];
__device__ __align__(128) float g_h[NN * DD];

// ---------------- PTX helpers (base ISA only) --------------------------------
__device__ __forceinline__ void red2(float* p, float x, float y) {
    asm volatile("red.global.add.v2.f32 [%0], {%1,%2};"
                 :: "l"(p), "f"(x), "f"(y) : "memory");
}
__device__ __forceinline__ uint32_t smem_u32(const void* p) {
    uint32_t a;
    asm("{ .reg .u64 t; cvta.to.shared.u64 t, %1; cvt.u32.u64 %0, t; }"
        : "=r"(a) : "l"(p));
    return a;
}
__device__ __forceinline__ void ldsm4(uint32_t& r0, uint32_t& r1,
                                      uint32_t& r2, uint32_t& r3, uint32_t a) {
    asm volatile("ldmatrix.sync.aligned.m8n8.x4.shared.b16 {%0,%1,%2,%3}, [%4];"
                 : "=r"(r0), "=r"(r1), "=r"(r2), "=r"(r3) : "r"(a));
}
__device__ __forceinline__ void mma16816(float* c,
                                         uint32_t a0, uint32_t a1, uint32_t a2, uint32_t a3,
                                         uint32_t b0, uint32_t b1) {
    asm volatile("mma.sync.aligned.m16n8k16.row.col.f32.bf16.bf16.f32 "
                 "{%0,%1,%2,%3}, {%4,%5,%6,%7}, {%8,%9}, {%0,%1,%2,%3};"
                 : "+f"(c[0]), "+f"(c[1]), "+f"(c[2]), "+f"(c[3])
                 : "r"(a0), "r"(a1), "r"(a2), "r"(a3), "r"(b0), "r"(b1));
}
__device__ __forceinline__ void cpa16(uint32_t dst, const void* src) {
    asm volatile("cp.async.cg.shared.global [%0], [%1], 16;"
                 :: "r"(dst), "l"(src) : "memory");
}
#define CPA_COMMIT() asm volatile("cp.async.commit_group;" ::: "memory")
#define CPA_WAIT(n)  asm volatile("cp.async.wait_group %0;" :: "n"(n) : "memory")
#define SWZ128(o) ((o) ^ (((o) >> 3) & 0x70))

// ---------------- CSR preprocessing (one-time) -------------------------------
__global__ void k_init() {
    int stride = gridDim.x * blockDim.x;
    for (int i = blockIdx.x * blockDim.x + threadIdx.x; i < NSEG; i += stride) {
        g_cnt[i] = 0; g_cur[i] = 0;
    }
    if (blockIdx.x == 0 && threadIdx.x < RR) g_listcnt[threadIdx.x] = 0;
}
__global__ void k_count(const int* __restrict__ dst, const int* __restrict__ et) {
    int e = blockIdx.x * blockDim.x + threadIdx.x;
    if (e < EE) atomicAdd(&g_cnt[et[e] * NN + dst[e]], 1);
}
__global__ void k_scan1() {
    __shared__ int sh[1024];
    int i = blockIdx.x * 1024 + threadIdx.x;
    int v = (i < NSEG) ? g_cnt[i] : 0;
    sh[threadIdx.x] = v; __syncthreads();
    #pragma unroll
    for (int d = 1; d < 1024; d <<= 1) {
        int t = (threadIdx.x >= d) ? sh[threadIdx.x - d] : 0;
        __syncthreads(); sh[threadIdx.x] += t; __syncthreads();
    }
    if (i < NSEG) g_off[i] = sh[threadIdx.x] - v;
    if (threadIdx.x == 1023) g_bsum[blockIdx.x] = sh[1023];
}
__global__ void k_scan2() {
    __shared__ int sh[1024];
    int v = (threadIdx.x < NBLK) ? g_bsum[threadIdx.x] : 0;
    sh[threadIdx.x] = v; __syncthreads();
    #pragma unroll
    for (int d = 1; d < 1024; d <<= 1) {
        int t = (threadIdx.x >= d) ? sh[threadIdx.x - d] : 0;
        __syncthreads(); sh[threadIdx.x] += t; __syncthreads();
    }
    g_bsum[threadIdx.x] = sh[threadIdx.x] - v;
}
__global__ void k_scan3() {
    int i = blockIdx.x * 1024 + threadIdx.x;
    if (i < NSEG) g_off[i] += g_bsum[blockIdx.x];
}
__global__ void k_fill(const int* __restrict__ src, const int* __restrict__ dst,
                       const int* __restrict__ et) {
    int e = blockIdx.x * blockDim.x + threadIdx.x;
    if (e >= EE) return;
    int seg = et[e] * NN + dst[e];
    g_srcids[g_off[seg] + atomicAdd(&g_cur[seg], 1)] = src[e];
}
__global__ void k_compact() {
    int i = blockIdx.x * blockDim.x + threadIdx.x;
    if (i >= NSEG) return;
    if (g_cnt[i] > 0) {
        int r = i / NN, n = i - r * NN;
        g_list[r * NN + atomicAdd(&g_listcnt[r], 1)] = n;
    }
}

// transpose+split weights: g_B?[slot][n][k] = W_slot[k][n]; slot 16 = root
__global__ void k_wsplit(const float* __restrict__ W, const float* __restrict__ root) {
    int i = blockIdx.x * blockDim.x + threadIdx.x;
    if (i >= 17 * DD * KPAD) return;
    int slot = i / (DD * KPAD);
    int rem = i - slot * DD * KPAD;
    int n = rem / KPAD, k = rem - n * KPAD;
    if (k >= 208) return;                // cols 208..255 never read
    float v = 0.f;
    if (k < DD) v = (slot < 16) ? W[(size_t)slot * DD * DD + k * DD + n]
                                : root[k * DD + n];
    __nv_bfloat16 h = __float2bfloat16(v);
    g_Bh[i] = h;
    g_Bl[i] = __float2bfloat16(v - __bfloat162float(h));
}

// ---------------- fused gather-mean + HMMA GEMM (M=64, 256 thr, occ 2) -------
// K chunk-major: for each of 4 K-chunks, gather A chunk (fp32 mean -> bf16
// hi/lo split, 16KB smem tile), then 2 B-stages through a cp.async double
// buffer: Bh (fused Ah*Bh + Al*Bh, B fragments ldsm'd once) then Bl (Ah*Bl).
// REL=false: identity rows, out = D + bias. REL=true: out[g_list] += D (red.v2)
// RELU: apply max(0,.) to xsrc reads (layer 2).
template <bool REL, bool RELU>
__global__ __launch_bounds__(256, 2)
void k_mma(const float* __restrict__ xsrc, const float* __restrict__ bias,
           float* __restrict__ out) {
    extern __shared__ char dsm[];
    const int r  = REL ? blockIdx.y : 0;
    const int m0 = blockIdx.x * 64;
    int valid = REL ? (g_listcnt[r] - m0) : (NN - m0);
    if (valid <= 0) return;
    if (valid > 64) valid = 64;
    const int slot = REL ? r : 16;

    const int tid  = threadIdx.x;
    const int wid  = tid >> 5, lane = tid & 31;
    const int mgrp = wid >> 1, ngrp = wid & 1;
    const int tb   = ngrp * 13;

    const uint32_t sbase = smem_u32(dsm);
    const __nv_bfloat16* Bh = g_Bh + (size_t)slot * DD * KPAD;
    const __nv_bfloat16* Bl = g_Bl + (size_t)slot * DD * KPAD;

    // async fill of B stage s (s = 2*ch + t) into buffer s&1
    auto fillB = [&](int s) {
        const int ch = s >> 1;
        const __nv_bfloat16* Bs = (s & 1) ? Bl : Bh;
        const uint32_t bB = sbase + B_OFF + (uint32_t)(s & 1) * BBYTES;
        if (ch < 3) {
            #pragma unroll
            for (int l = 0; l < 7; l++) {               // 200 rows x 8 x 16B
                int u = tid + l * 256;
                if (u < 1600) {
                    int row = u >> 3, g = u & 7;
                    cpa16(bB + SWZ128((uint32_t)(row * 128 + g * 16)),
                          Bs + (size_t)row * KPAD + ch * 64 + g * 8);
                }
            }
        } else {
            #pragma unroll
            for (int l = 0; l < 2; l++) {               // 200 rows x 2 x 16B
                int u = tid + l * 256;
                if (u < 400) {
                    int row = u >> 1, g = u & 1;
                    cpa16(bB + SWZ128((uint32_t)(row * 128 + g * 16)),
                          Bs + (size_t)row * KPAD + 192 + g * 8);
                }
            }
        }
    };

    // gather A chunk ch: half-warp per row (2 rows per j-iter), 16 lanes x 4 cols
    auto gatherA = [&](int ch) {
        const int half = lane >> 4, sl = lane & 15;
        const int colbase = ch * 64 + sl * 4;
        const bool cok = colbase < 200;
        #pragma unroll 1
        for (int j = 0; j < 4; j++) {
            const int row = wid * 8 + j * 2 + half;
            float s0[4] = {0.f, 0.f, 0.f, 0.f};
            if (row < valid && cok) {
                if (REL) {
                    int n = g_list[r * NN + m0 + row];
                    int seg = r * NN + n;
                    int o0 = g_off[seg], deg = g_cnt[seg];
                    for (int e = 0; e < deg; e++) {
                        float4 v = *(const float4*)(xsrc +
                            (size_t)g_srcids[o0 + e] * DD + colbase);
                        if (RELU) {
                            v.x = fmaxf(v.x, 0.f); v.y = fmaxf(v.y, 0.f);
                            v.z = fmaxf(v.z, 0.f); v.w = fmaxf(v.w, 0.f);
                        }
                        s0[0] += v.x; s0[1] += v.y; s0[2] += v.z; s0[3] += v.w;
                    }
                    float inv = 1.0f / (float)deg;
                    #pragma unroll
                    for (int i = 0; i < 4; i++) s0[i] *= inv;
                } else {
                    float4 v = *(const float4*)(xsrc +
                        (size_t)(m0 + row) * DD + colbase);
                    if (RELU) {
                        v.x = fmaxf(v.x, 0.f); v.y = fmaxf(v.y, 0.f);
                        v.z = fmaxf(v.z, 0.f); v.w = fmaxf(v.w, 0.f);
                    }
                    s0[0] = v.x; s0[1] = v.y; s0[2] = v.z; s0[3] = v.w;
                }
            }
            __nv_bfloat16 hp[4], lp[4];
            #pragma unroll
            for (int i = 0; i < 4; i++) {
                hp[i] = __float2bfloat16(s0[i]);
                lp[i] = __float2bfloat16(s0[i] - __bfloat162float(hp[i]));
            }
            const uint32_t sw = SWZ128((uint32_t)(row * 128 + sl * 8));
            *(uint2*)(dsm + sw)         = *(const uint2*)hp;
            *(uint2*)(dsm + ATILE + sw) = *(const uint2*)lp;
        }
    };

    // ldmatrix lane-address components
    const int lg = lane >> 3, rs = lane & 7;
    const uint32_t a_row = mgrp * 16 + ((lg & 1) << 3) + rs;
    const uint32_t a_kb  = (uint32_t)(lg >> 1) << 4;
    const uint32_t b_ro  = ((uint32_t)(lg >> 1) << 3) + rs;
    const uint32_t b_kb  = (uint32_t)(lg & 1) << 4;

    float acc[14][4];
    #pragma unroll
    for (int i = 0; i < 14; i++)
        #pragma unroll
        for (int j = 0; j < 4; j++) acc[i][j] = 0.f;

    fillB(0);
    CPA_COMMIT();

    #pragma unroll 1
    for (int ch = 0; ch < 4; ch++) {
        gatherA(ch);      // A buffer free: previous chunk's MMA ended at a barrier
        const int nk16 = (ch < 3) ? 4 : 1;
        #pragma unroll 1
        for (int t = 0; t < 2; t++) {
            const int s = 2 * ch + t;
            if (s < 7) {
                fillB(s + 1);
                CPA_COMMIT();
                CPA_WAIT(1);
            } else {
                CPA_WAIT(0);
            }
            __syncthreads();   // B[s] + gathered A visible

            const uint32_t bB = sbase + B_OFF + (uint32_t)(s & 1) * BBYTES;
            #pragma unroll 1
            for (int k16 = 0; k16 < nk16; k16++) {
                const uint32_t kbase = (uint32_t)k16 * 32;
                uint32_t h0, h1, h2, h3;
                ldsm4(h0, h1, h2, h3, sbase + SWZ128(a_row * 128 + kbase + a_kb));
                if (t == 0) {
                    uint32_t l0, l1, l2, l3;
                    ldsm4(l0, l1, l2, l3,
                          sbase + ATILE + SWZ128(a_row * 128 + kbase + a_kb));
                    #pragma unroll
                    for (int p = 0; p < 7; p++) {
                        uint32_t b0, b1, b2, b3;
                        uint32_t nrow = (uint32_t)(tb + 2 * p) * 8 + b_ro;
                        ldsm4(b0, b1, b2, b3, bB + SWZ128(nrow * 128 + kbase + b_kb));
                        mma16816(acc[2 * p],     h0, h1, h2, h3, b0, b1);
                        mma16816(acc[2 * p + 1], h0, h1, h2, h3, b2, b3);
                        mma16816(acc[2 * p],     l0, l1, l2, l3, b0, b1);
                        mma16816(acc[2 * p + 1], l0, l1, l2, l3, b2, b3);
                    }
                } else {
                    #pragma unroll
                    for (int p = 0; p < 7; p++) {
                        uint32_t b0, b1, b2, b3;
                        uint32_t nrow = (uint32_t)(tb + 2 * p) * 8 + b_ro;
                        ldsm4(b0, b1, b2, b3, bB + SWZ128(nrow * 128 + kbase + b_kb));
                        mma16816(acc[2 * p],     h0, h1, h2, h3, b0, b1);
                        mma16816(acc[2 * p + 1], h0, h1, h2, h3, b2, b3);
                    }
                }
            }
            __syncthreads();   // B buffer s&1 free for refill; A reusable after t=1
        }
    }

    // ---- epilogue ----
    const int rlo = lane >> 2;
    const int cq  = (lane & 3) * 2;
    const int ntl = ngrp ? 12 : 13;
    #pragma unroll
    for (int h = 0; h < 2; h++) {
        int lrow = mgrp * 16 + rlo + h * 8;
        if (lrow < valid) {
            int n = REL ? g_list[r * NN + m0 + lrow] : (m0 + lrow);
            float* op = out + (size_t)n * DD;
            #pragma unroll
            for (int tl = 0; tl < 13; tl++) {
                if (tl < ntl) {
                    int col = (tb + tl) * 8 + cq;
                    if (REL) {
                        red2(op + col, acc[tl][h * 2], acc[tl][h * 2 + 1]);
                    } else {
                        float2 bv = *(const float2*)(bias + col);
                        float2 v;
                        v.x = acc[tl][h * 2]     + bv.x;
                        v.y = acc[tl][h * 2 + 1] + bv.y;
                        *(float2*)(op + col) = v;
                    }
                }
            }
        }
    }
}

// ---------------- launch -------------------------------------------------------
extern "C" void kernel_launch(void* const* d_in, const int* in_sizes, int n_in,
                              void* d_out, int out_size) {
    const int*   ei    = (const int*)d_in[0];
    const int*   et    = (const int*)d_in[1];
    const float* emb   = (const float*)d_in[2];
    const float* W1    = (const float*)d_in[3];
    const float* root1 = (const float*)d_in[4];
    const float* b1    = (const float*)d_in[5];
    const float* W2    = (const float*)d_in[6];
    const float* root2 = (const float*)d_in[7];
    const float* b2    = (const float*)d_in[8];
    float* out = (float*)d_out;

    const int* src = ei;
    const int* dst = ei + EE;

    float* hptr = nullptr;
    cudaGetSymbolAddress((void**)&hptr, g_h);

    cudaFuncSetAttribute(k_mma<false, false>, cudaFuncAttributeMaxDynamicSharedMemorySize, SMEM_TOTAL);
    cudaFuncSetAttribute(k_mma<true,  false>, cudaFuncAttributeMaxDynamicSharedMemorySize, SMEM_TOTAL);
    cudaFuncSetAttribute(k_mma<false, true >, cudaFuncAttributeMaxDynamicSharedMemorySize, SMEM_TOTAL);
    cudaFuncSetAttribute(k_mma<true,  true >, cudaFuncAttributeMaxDynamicSharedMemorySize, SMEM_TOTAL);

    const int mb = (NN + 63) / 64;              // 782
    const int eb = (EE + 255) / 256;
    const int sb = (NSEG + 255) / 256;
    const int ws = (17 * DD * KPAD + 255) / 256;

    k_wsplit<<<ws, 256>>>(W1, root1);
    k_init<<<1024, 256>>>();
    k_count<<<eb, 256>>>(dst, et);
    k_scan1<<<NBLK, 1024>>>();
    k_scan2<<<1, 1024>>>();
    k_mma<false, false><<<dim3(mb, 1), 256, SMEM_TOTAL>>>(emb, b1, hptr);
    k_scan3<<<NBLK, 1024>>>();
    k_fill<<<eb, 256>>>(src, dst, et);
    k_compact<<<sb, 256>>>();
    k_mma<true, false><<<dim3(mb, RR), 256, SMEM_TOTAL>>>(emb, nullptr, hptr);
    k_wsplit<<<ws, 256>>>(W2, root2);
    k_mma<false, true><<<dim3(mb, 1), 256, SMEM_TOTAL>>>(hptr, b2, out);
    k_mma<true, true ><<<dim3(mb, RR), 256, SMEM_TOTAL>>>(hptr, nullptr, out);
}

// round 17
// speedup vs baseline: 1.2331x; 1.2331x over previous
#include <cuda_runtime.h>
#include <cuda_fp16.h>
#include <cstdint>

#define NN 50000
#define RR 16
#define DD 200
#define EE 400000
#define KPAD 256

#define NSEG (RR * NN)
#define NBLK ((NSEG + 1023) / 1024)

#define ATILE 16384                     // one 128-row x 128B chunk tile
#define AH_OFF 0                        // 4 chunk tiles: 64KB
#define AL_OFF (4 * ATILE)              // 4 chunk tiles: 64KB
#define B_OFF  (8 * ATILE)              // double buffer
#define BBYTES 27648                    // 216 rows x 128B
#define SMEM_TOTAL (B_OFF + 2 * BBYTES) // 186368

// ---------------- scratch (device globals) ----------------------------------
__device__ __align__(128) __half g_B[17 * DD * KPAD];   // [slot][n][k], slot16=root
__device__ int   g_cnt[NSEG];
__device__ int   g_cur[NSEG];
__device__ int   g_off[NSEG];
__device__ int   g_bsum[1024];
__device__ int   g_srcids[EE];
__device__ int   g_list[NSEG];
__device__ int   g_listcnt[RR];
__device__ __align__(128) float g_h[NN * DD];

// ---------------- PTX helpers (base ISA only) --------------------------------
__device__ __forceinline__ void red2(float* p, float x, float y) {
    asm volatile("red.global.add.v2.f32 [%0], {%1,%2};"
                 :: "l"(p), "f"(x), "f"(y) : "memory");
}
__device__ __forceinline__ uint32_t smem_u32(const void* p) {
    uint32_t a;
    asm("{ .reg .u64 t; cvta.to.shared.u64 t, %1; cvt.u32.u64 %0, t; }"
        : "=r"(a) : "l"(p));
    return a;
}
__device__ __forceinline__ void ldsm4(uint32_t& r0, uint32_t& r1,
                                      uint32_t& r2, uint32_t& r3, uint32_t a) {
    asm volatile("ldmatrix.sync.aligned.m8n8.x4.shared.b16 {%0,%1,%2,%3}, [%4];"
                 : "=r"(r0), "=r"(r1), "=r"(r2), "=r"(r3) : "r"(a));
}
__device__ __forceinline__ void mma16816(float* c,
                                         uint32_t a0, uint32_t a1, uint32_t a2, uint32_t a3,
                                         uint32_t b0, uint32_t b1) {
    asm volatile("mma.sync.aligned.m16n8k16.row.col.f32.f16.f16.f32 "
                 "{%0,%1,%2,%3}, {%4,%5,%6,%7}, {%8,%9}, {%0,%1,%2,%3};"
                 : "+f"(c[0]), "+f"(c[1]), "+f"(c[2]), "+f"(c[3])
                 : "r"(a0), "r"(a1), "r"(a2), "r"(a3), "r"(b0), "r"(b1));
}
__device__ __forceinline__ void cpa16(uint32_t dst, const void* src) {
    asm volatile("cp.async.cg.shared.global [%0], [%1], 16;"
                 :: "r"(dst), "l"(src) : "memory");
}
#define CPA_COMMIT() asm volatile("cp.async.commit_group;" ::: "memory")
#define CPA_WAIT(n)  asm volatile("cp.async.wait_group %0;" :: "n"(n) : "memory")
#define SWZ128(o) ((o) ^ (((o) >> 3) & 0x70))

// ---------------- CSR preprocessing (one-time) -------------------------------
__global__ void k_init() {
    int stride = gridDim.x * blockDim.x;
    for (int i = blockIdx.x * blockDim.x + threadIdx.x; i < NSEG; i += stride) {
        g_cnt[i] = 0; g_cur[i] = 0;
    }
    if (blockIdx.x == 0 && threadIdx.x < RR) g_listcnt[threadIdx.x] = 0;
}
__global__ void k_count(const int* __restrict__ dst, const int* __restrict__ et) {
    int e = blockIdx.x * blockDim.x + threadIdx.x;
    if (e < EE) atomicAdd(&g_cnt[et[e] * NN + dst[e]], 1);
}
__global__ void k_scan1() {
    __shared__ int sh[1024];
    int i = blockIdx.x * 1024 + threadIdx.x;
    int v = (i < NSEG) ? g_cnt[i] : 0;
    sh[threadIdx.x] = v; __syncthreads();
    #pragma unroll
    for (int d = 1; d < 1024; d <<= 1) {
        int t = (threadIdx.x >= d) ? sh[threadIdx.x - d] : 0;
        __syncthreads(); sh[threadIdx.x] += t; __syncthreads();
    }
    if (i < NSEG) g_off[i] = sh[threadIdx.x] - v;
    if (threadIdx.x == 1023) g_bsum[blockIdx.x] = sh[1023];
}
__global__ void k_scan2() {
    __shared__ int sh[1024];
    int v = (threadIdx.x < NBLK) ? g_bsum[threadIdx.x] : 0;
    sh[threadIdx.x] = v; __syncthreads();
    #pragma unroll
    for (int d = 1; d < 1024; d <<= 1) {
        int t = (threadIdx.x >= d) ? sh[threadIdx.x - d] : 0;
        __syncthreads(); sh[threadIdx.x] += t; __syncthreads();
    }
    g_bsum[threadIdx.x] = sh[threadIdx.x] - v;
}
__global__ void k_scan3() {
    int i = blockIdx.x * 1024 + threadIdx.x;
    if (i < NSEG) g_off[i] += g_bsum[blockIdx.x];
}
__global__ void k_fill(const int* __restrict__ src, const int* __restrict__ dst,
                       const int* __restrict__ et) {
    int e = blockIdx.x * blockDim.x + threadIdx.x;
    if (e >= EE) return;
    int seg = et[e] * NN + dst[e];
    g_srcids[g_off[seg] + atomicAdd(&g_cur[seg], 1)] = src[e];
}
__global__ void k_compact() {
    int i = blockIdx.x * blockDim.x + threadIdx.x;
    if (i >= NSEG) return;
    if (g_cnt[i] > 0) {
        int r = i / NN, n = i - r * NN;
        g_list[r * NN + atomicAdd(&g_listcnt[r], 1)] = n;
    }
}

// transpose weights to fp16: g_B[slot][n][k] = W_slot[k][n]; slot 16 = root
__global__ void k_wsplit(const float* __restrict__ W, const float* __restrict__ root) {
    int i = blockIdx.x * blockDim.x + threadIdx.x;
    if (i >= 17 * DD * KPAD) return;
    int slot = i / (DD * KPAD);
    int rem = i - slot * DD * KPAD;
    int n = rem / KPAD, k = rem - n * KPAD;
    if (k >= 208) return;                // cols 208..255 never read
    float v = 0.f;
    if (k < DD) v = (slot < 16) ? W[(size_t)slot * DD * DD + k * DD + n]
                                : root[k * DD + n];
    g_B[i] = __float2half(v);
}

// ---------------- fused gather-mean + HMMA GEMM (fp16 2-pass split) ----------
// A gathered in prologue (fp32 mean -> fp16 hi/lo split), resident in smem as
// 4 chunk tiles per half. B (single fp16, pre-transposed W) streams through a
// cp.async double buffer in 4 stages; each stage runs the fused (Ah+Al)*B MMA
// (B fragments ldsm'd once, used by both A terms). 26 k16-MMA units total.
// REL=false: identity rows, out = D + bias (store)
// REL=true : rows = active (r,seg) list, out[g_list] += D (red.global.v2)
// RELU: apply max(0,.) to xsrc reads (layer 2).
template <bool REL, bool RELU>
__global__ __launch_bounds__(512)
void k_mma(const float* __restrict__ xsrc, const float* __restrict__ bias,
           float* __restrict__ out) {
    extern __shared__ char dsm[];
    const int r  = REL ? blockIdx.y : 0;
    const int m0 = blockIdx.x * 128;
    int valid = REL ? (g_listcnt[r] - m0) : (NN - m0);
    if (valid <= 0) return;
    if (valid > 128) valid = 128;
    const int slot = REL ? r : 16;

    const int tid  = threadIdx.x;
    const int wid  = tid >> 5, lane = tid & 31;
    const int mgrp = wid >> 1, ngrp = wid & 1;
    const int tb   = ngrp * 13;

    const uint32_t sbase = smem_u32(dsm);
    const __half* Bp = g_B + (size_t)slot * DD * KPAD;

    // async fill of B chunk s into buffer s&1
    auto fillB = [&](int s) {
        const uint32_t bB = sbase + B_OFF + (uint32_t)(s & 1) * BBYTES;
        if (s < 3) {
            #pragma unroll
            for (int l = 0; l < 4; l++) {
                int u = tid + l * 512;
                if (u < 1600) {
                    int row = u >> 3, g = u & 7;
                    cpa16(bB + SWZ128((uint32_t)(row * 128 + g * 16)),
                          Bp + (size_t)row * KPAD + s * 64 + g * 8);
                }
            }
        } else {
            if (tid < 400) {
                int row = tid >> 1, g = tid & 1;
                cpa16(bB + SWZ128((uint32_t)(row * 128 + g * 16)),
                      Bp + (size_t)row * KPAD + 192 + g * 8);
            }
        }
    };

    fillB(0);
    CPA_COMMIT();

    // ---- gather A: warp w handles rows w, w+16, ..., w+112 ----
    // lane l < 25: cols l*8..l*8+7 (fp32 mean, optional relu, split to fp16)
    // lane 25: zero-pad cols 200..207; lanes 26..31 idle
    #pragma unroll 1
    for (int j = 0; j < 8; j++) {
        const int row = wid + j * 16;
        float s0[8];
        #pragma unroll
        for (int i = 0; i < 8; i++) s0[i] = 0.f;

        if (row < valid && lane < 25) {
            if (REL) {
                int n = g_list[r * NN + m0 + row];
                int seg = r * NN + n;
                int o0 = g_off[seg], deg = g_cnt[seg];
                for (int e = 0; e < deg; e++) {
                    const float4* xr = (const float4*)(xsrc +
                        (size_t)g_srcids[o0 + e] * DD + lane * 8);
                    float4 v0 = xr[0], v1 = xr[1];
                    if (RELU) {
                        v0.x = fmaxf(v0.x, 0.f); v0.y = fmaxf(v0.y, 0.f);
                        v0.z = fmaxf(v0.z, 0.f); v0.w = fmaxf(v0.w, 0.f);
                        v1.x = fmaxf(v1.x, 0.f); v1.y = fmaxf(v1.y, 0.f);
                        v1.z = fmaxf(v1.z, 0.f); v1.w = fmaxf(v1.w, 0.f);
                    }
                    s0[0] += v0.x; s0[1] += v0.y; s0[2] += v0.z; s0[3] += v0.w;
                    s0[4] += v1.x; s0[5] += v1.y; s0[6] += v1.z; s0[7] += v1.w;
                }
                float inv = 1.0f / (float)deg;
                #pragma unroll
                for (int i = 0; i < 8; i++) s0[i] *= inv;
            } else {
                const float4* xr = (const float4*)(xsrc +
                    (size_t)(m0 + row) * DD + lane * 8);
                float4 v0 = xr[0], v1 = xr[1];
                if (RELU) {
                    v0.x = fmaxf(v0.x, 0.f); v0.y = fmaxf(v0.y, 0.f);
                    v0.z = fmaxf(v0.z, 0.f); v0.w = fmaxf(v0.w, 0.f);
                    v1.x = fmaxf(v1.x, 0.f); v1.y = fmaxf(v1.y, 0.f);
                    v1.z = fmaxf(v1.z, 0.f); v1.w = fmaxf(v1.w, 0.f);
                }
                s0[0] = v0.x; s0[1] = v0.y; s0[2] = v0.z; s0[3] = v0.w;
                s0[4] = v1.x; s0[5] = v1.y; s0[6] = v1.z; s0[7] = v1.w;
            }
        }
        if (lane < 26) {
            __half hp[8], lp[8];
            #pragma unroll
            for (int i = 0; i < 8; i++) {
                hp[i] = __float2half(s0[i]);
                lp[i] = __float2half(s0[i] - __half2float(hp[i]));
            }
            const int cb = lane * 8;
            const uint32_t sw = SWZ128((uint32_t)(row * 128 + (cb & 63) * 2));
            const uint32_t tbase = (uint32_t)(cb >> 6) * ATILE;
            *(uint4*)(dsm + AH_OFF + tbase + sw) = *(const uint4*)hp;
            *(uint4*)(dsm + AL_OFF + tbase + sw) = *(const uint4*)lp;
        }
    }

    // ldmatrix lane-address components
    const int lg = lane >> 3, rs = lane & 7;
    const uint32_t a_row = mgrp * 16 + ((lg & 1) << 3) + rs;
    const uint32_t a_kb  = (uint32_t)(lg >> 1) << 4;
    const uint32_t b_ro  = ((uint32_t)(lg >> 1) << 3) + rs;
    const uint32_t b_kb  = (uint32_t)(lg & 1) << 4;

    float acc[14][4];
    #pragma unroll
    for (int i = 0; i < 14; i++)
        #pragma unroll
        for (int j = 0; j < 4; j++) acc[i][j] = 0.f;

    __syncthreads();   // A resident & visible

    #pragma unroll 1
    for (int s = 0; s < 4; s++) {
        if (s < 3) {
            fillB(s + 1);
            CPA_COMMIT();
            CPA_WAIT(1);
        } else {
            CPA_WAIT(0);
        }
        __syncthreads();

        const uint32_t bB = sbase + B_OFF + (uint32_t)(s & 1) * BBYTES;
        const uint32_t aH = sbase + AH_OFF + (uint32_t)s * ATILE;
        const uint32_t aL = sbase + AL_OFF + (uint32_t)s * ATILE;
        const int nk16 = (s < 3) ? 4 : 1;
        #pragma unroll 1
        for (int k16 = 0; k16 < nk16; k16++) {
            const uint32_t kbase = (uint32_t)k16 * 32;
            uint32_t h0, h1, h2, h3, l0, l1, l2, l3;
            ldsm4(h0, h1, h2, h3, aH + SWZ128(a_row * 128 + kbase + a_kb));
            ldsm4(l0, l1, l2, l3, aL + SWZ128(a_row * 128 + kbase + a_kb));
            #pragma unroll
            for (int p = 0; p < 7; p++) {
                uint32_t b0, b1, b2, b3;
                uint32_t nrow = (uint32_t)(tb + 2 * p) * 8 + b_ro;
                ldsm4(b0, b1, b2, b3, bB + SWZ128(nrow * 128 + kbase + b_kb));
                mma16816(acc[2 * p],     h0, h1, h2, h3, b0, b1);
                mma16816(acc[2 * p + 1], h0, h1, h2, h3, b2, b3);
                mma16816(acc[2 * p],     l0, l1, l2, l3, b0, b1);
                mma16816(acc[2 * p + 1], l0, l1, l2, l3, b2, b3);
            }
        }
        __syncthreads();   // buffer s&1 free for refill
    }

    // ---- epilogue ----
    const int rlo = lane >> 2;
    const int cq  = (lane & 3) * 2;
    const int ntl = ngrp ? 12 : 13;
    #pragma unroll
    for (int h = 0; h < 2; h++) {
        int lrow = mgrp * 16 + rlo + h * 8;
        if (lrow < valid) {
            int n = REL ? g_list[r * NN + m0 + lrow] : (m0 + lrow);
            float* op = out + (size_t)n * DD;
            #pragma unroll
            for (int tl = 0; tl < 13; tl++) {
                if (tl < ntl) {
                    int col = (tb + tl) * 8 + cq;
                    if (REL) {
                        red2(op + col, acc[tl][h * 2], acc[tl][h * 2 + 1]);
                    } else {
                        float2 bv = *(const float2*)(bias + col);
                        float2 v;
                        v.x = acc[tl][h * 2]     + bv.x;
                        v.y = acc[tl][h * 2 + 1] + bv.y;
                        *(float2*)(op + col) = v;
                    }
                }
            }
        }
    }
}

// ---------------- launch -------------------------------------------------------
extern "C" void kernel_launch(void* const* d_in, const int* in_sizes, int n_in,
                              void* d_out, int out_size) {
    const int*   ei    = (const int*)d_in[0];
    const int*   et    = (const int*)d_in[1];
    const float* emb   = (const float*)d_in[2];
    const float* W1    = (const float*)d_in[3];
    const float* root1 = (const float*)d_in[4];
    const float* b1    = (const float*)d_in[5];
    const float* W2    = (const float*)d_in[6];
    const float* root2 = (const float*)d_in[7];
    const float* b2    = (const float*)d_in[8];
    float* out = (float*)d_out;

    const int* src = ei;
    const int* dst = ei + EE;

    float* hptr = nullptr;
    cudaGetSymbolAddress((void**)&hptr, g_h);

    cudaFuncSetAttribute(k_mma<false, false>, cudaFuncAttributeMaxDynamicSharedMemorySize, SMEM_TOTAL);
    cudaFuncSetAttribute(k_mma<true,  false>, cudaFuncAttributeMaxDynamicSharedMemorySize, SMEM_TOTAL);
    cudaFuncSetAttribute(k_mma<false, true >, cudaFuncAttributeMaxDynamicSharedMemorySize, SMEM_TOTAL);
    cudaFuncSetAttribute(k_mma<true,  true >, cudaFuncAttributeMaxDynamicSharedMemorySize, SMEM_TOTAL);

    const int mb = (NN + 127) / 128;            // 391
    const int eb = (EE + 255) / 256;
    const int sb = (NSEG + 255) / 256;
    const int ws = (17 * DD * KPAD + 255) / 256;

    // root-L1 k_mma placed at launch index 3 (the slot ncu profiles)
    k_wsplit<<<ws, 256>>>(W1, root1);                                     // 0
    k_init<<<1024, 256>>>();                                              // 1
    k_count<<<eb, 256>>>(dst, et);                                        // 2
    k_mma<false, false><<<dim3(mb, 1), 512, SMEM_TOTAL>>>(emb, b1, hptr); // 3 <- profile
    k_scan1<<<NBLK, 1024>>>();                                            // 4
    k_scan2<<<1, 1024>>>();                                               // 5
    k_scan3<<<NBLK, 1024>>>();                                            // 6
    k_fill<<<eb, 256>>>(src, dst, et);                                    // 7
    k_compact<<<sb, 256>>>();                                             // 8
    k_mma<true, false><<<dim3(mb, RR), 512, SMEM_TOTAL>>>(emb, nullptr, hptr); // 9
    k_wsplit<<<ws, 256>>>(W2, root2);                                     // 10
    k_mma<false, true><<<dim3(mb, 1), 512, SMEM_TOTAL>>>(hptr, b2, out);        // 11
    k_mma<true, true ><<<dim3(mb, RR), 512, SMEM_TOTAL>>>(hptr, nullptr, out);  // 12
}